// round 2
// baseline (speedup 1.0000x reference)
#include <cuda_runtime.h>

// PatchGramPreprocessing: per patch n, per layer:
//   fr[cr][p]  = mean over K=C/64 consecutive channels of feat[n, cr*K+j, p]
//   s[g][p]    = sum of 4 consecutive fr rows (output pooling folded in)
//   out[cr*16+g] = (1/(4*9)) * sum_p fr[cr][p] * s[g][p]
// Output layout: out[n][layer][1024], layers stacked on axis 1.

template <int C>
__global__ __launch_bounds__(256)
void gram_kernel(const float* __restrict__ feat, float* __restrict__ out, int layer)
{
    constexpr int P  = 9;
    constexpr int K  = C / 64;       // channels per pooled group
    constexpr int NF = C * P;        // floats per patch (4608 or 9216)

    __shared__ float buf[NF];        // staged input blob (18 KB / 36 KB)
    __shared__ float fr[64][12];     // padded rows to spread banks
    __shared__ float sg[16][12];

    const int n   = blockIdx.x;
    const int tid = threadIdx.x;

    // ---- coalesced streaming load: blob is contiguous and 16B-aligned ----
    const float4* src = reinterpret_cast<const float4*>(feat) + (size_t)n * (NF / 4);
    float4* dst = reinterpret_cast<float4*>(buf);
    for (int i = tid; i < NF / 4; i += 256)
        dst[i] = __ldcs(src + i);
    __syncthreads();

    // ---- channel-group reduction: fr[cr][p] ----
    for (int i = tid; i < 64 * P; i += 256) {
        int cr = i / P;
        int p  = i - cr * P;
        const float* b = buf + (cr * K) * P + p;
        float acc = 0.0f;
#pragma unroll
        for (int j = 0; j < K; j++)
            acc += b[j * P];
        fr[cr][p] = acc * (1.0f / (float)K);
    }
    __syncthreads();

    // ---- fold output pooling: sg[g][p] = sum of 4 consecutive fr rows ----
    if (tid < 16 * P) {
        int g = tid / P;
        int p = tid - g * P;
        sg[g][p] = fr[4 * g + 0][p] + fr[4 * g + 1][p]
                 + fr[4 * g + 2][p] + fr[4 * g + 3][p];
    }
    __syncthreads();

    // ---- tiny contraction + coalesced store ----
    constexpr float scale = 1.0f / (4.0f * (float)P);
    float* o = out + (size_t)n * 2048 + (size_t)layer * 1024;
    for (int i = tid; i < 1024; i += 256) {
        int cr = i >> 4;
        int g  = i & 15;
        float acc = 0.0f;
#pragma unroll
        for (int p = 0; p < P; p++)
            acc += fr[cr][p] * sg[g][p];
        o[i] = acc * scale;
    }
}

extern "C" void kernel_launch(void* const* d_in, const int* in_sizes, int n_in,
                              void* d_out, int out_size)
{
    const float* feat0 = (const float*)d_in[0];   // [N, 512, 3, 3]
    const float* feat1 = (const float*)d_in[1];   // [N, 1024, 3, 3]
    float* out = (float*)d_out;                   // [N, 2, 1024]

    const int N = in_sizes[0] / (512 * 9);

    gram_kernel<512><<<N, 256>>>(feat0, out, 0);
    gram_kernel<1024><<<N, 256>>>(feat1, out, 1);
}

// round 3
// speedup vs baseline: 1.4286x; 1.4286x over previous
#include <cuda_runtime.h>
#include <cstdint>

// Persistent, double-buffered (cp.async.bulk) PatchGram kernel.
// Per patch n, per layer:
//   fr[cr][p]  = mean over K=C/64 consecutive channels of feat[n, cr*K+j, p]
//   sg[g][p]   = sum of 4 consecutive fr rows (output pooling folded in)
//   out[cr*16+g] = (1/(4*9)) * sum_p fr[cr][p] * sg[g][p]
// Output layout: out[n][layer][1024].

__device__ __forceinline__ uint32_t smem_u32(const void* p) {
    return (uint32_t)__cvta_generic_to_shared(p);
}

__device__ __forceinline__ void mbar_init(uint32_t a, uint32_t cnt) {
    asm volatile("mbarrier.init.shared.b64 [%0], %1;" :: "r"(a), "r"(cnt) : "memory");
}

__device__ __forceinline__ void mbar_expect_tx(uint32_t a, uint32_t bytes) {
    asm volatile("mbarrier.arrive.expect_tx.shared.b64 _, [%0], %1;"
                 :: "r"(a), "r"(bytes) : "memory");
}

__device__ __forceinline__ void mbar_wait(uint32_t a, uint32_t phase) {
    asm volatile(
        "{\n\t"
        ".reg .pred p;\n\t"
        "WAIT_%=:\n\t"
        "mbarrier.try_wait.parity.acquire.cta.shared::cta.b64 p, [%0], %1, 0x989680;\n\t"
        "@p bra DONE_%=;\n\t"
        "bra WAIT_%=;\n\t"
        "DONE_%=:\n\t"
        "}"
        :: "r"(a), "r"(phase) : "memory");
}

// 1-D bulk async copy gmem -> smem (UBLKCP), completion via mbarrier tx bytes.
__device__ __forceinline__ void bulk_g2s(uint32_t dst_smem, const void* src_gmem,
                                         uint32_t bytes, uint32_t mbar) {
    asm volatile(
        "cp.async.bulk.shared::cluster.global.mbarrier::complete_tx::bytes "
        "[%0], [%1], %2, [%3];"
        :: "r"(dst_smem), "l"(src_gmem), "r"(bytes), "r"(mbar) : "memory");
}

template <int C>
__global__ __launch_bounds__(256)
void gram_kernel(const float* __restrict__ feat, float* __restrict__ out,
                 int layer, int N)
{
    constexpr int P  = 9;
    constexpr int K  = C / 64;
    constexpr int NF = C * P;                 // floats per patch
    constexpr uint32_t BYTES = NF * 4u;       // bytes per patch (16-aligned)

    extern __shared__ float buf[];            // [2][NF] double-buffered blob
    __shared__ float fr[64][12];
    __shared__ float sg[16][12];
    __shared__ alignas(8) unsigned long long mbar_s[2];

    const int tid = threadIdx.x;
    const uint32_t mb[2] = { smem_u32(&mbar_s[0]), smem_u32(&mbar_s[1]) };
    const uint32_t bufa  = smem_u32(buf);

    if (tid == 0) { mbar_init(mb[0], 1); mbar_init(mb[1], 1); }
    __syncthreads();

    const int j0     = blockIdx.x;
    const int stride = gridDim.x;

    // Prologue: prefetch first patch into stage 0.
    if (tid == 0 && j0 < N) {
        mbar_expect_tx(mb[0], BYTES);
        bulk_g2s(bufa, feat + (size_t)j0 * NF, BYTES, mb[0]);
    }

    int ph[2] = {0, 0};
    int s = 0;

    for (int j = j0; j < N; j += stride) {
        // Prefetch next patch into the other stage. Safe: that stage's last
        // readers finished before the __syncthreads ending the previous
        // iteration, and its mbarrier phase was consumed there too.
        const int jn = j + stride;
        if (tid == 0 && jn < N) {
            mbar_expect_tx(mb[s ^ 1], BYTES);
            bulk_g2s(bufa + (uint32_t)(s ^ 1) * BYTES,
                     feat + (size_t)jn * NF, BYTES, mb[s ^ 1]);
        }

        // Wait for current stage's data.
        mbar_wait(mb[s], ph[s]);
        ph[s] ^= 1;

        const float* b0 = buf + s * NF;

        // ---- channel-group reduction: fr[cr][p] ----
        for (int i = tid; i < 64 * P; i += 256) {
            int cr = i / P;
            int p  = i - cr * P;
            const float* b = b0 + (cr * K) * P + p;
            float acc = 0.0f;
#pragma unroll
            for (int q = 0; q < K; q++)
                acc += b[q * P];
            fr[cr][p] = acc * (1.0f / (float)K);
        }
        __syncthreads();

        // ---- fold output pooling: sg[g][p] = sum of 4 consecutive fr rows ----
        if (tid < 16 * P) {
            int g = tid / P;
            int p = tid - g * P;
            sg[g][p] = fr[4 * g + 0][p] + fr[4 * g + 1][p]
                     + fr[4 * g + 2][p] + fr[4 * g + 3][p];
        }
        __syncthreads();

        // ---- tiny contraction + coalesced streaming store ----
        constexpr float scale = 1.0f / (4.0f * (float)P);
        float* o = out + (size_t)j * 2048 + (size_t)layer * 1024;
        for (int i = tid; i < 1024; i += 256) {
            int cr = i >> 4;
            int g  = i & 15;
            float acc = 0.0f;
#pragma unroll
            for (int p = 0; p < P; p++)
                acc += fr[cr][p] * sg[g][p];
            __stcs(o + i, acc * scale);
        }

        // End-of-iteration barrier: protects fr/sg rewrite and stage reuse.
        __syncthreads();
        s ^= 1;
    }
}

extern "C" void kernel_launch(void* const* d_in, const int* in_sizes, int n_in,
                              void* d_out, int out_size)
{
    const float* feat0 = (const float*)d_in[0];   // [N, 512, 3, 3]
    const float* feat1 = (const float*)d_in[1];   // [N, 1024, 3, 3]
    float* out = (float*)d_out;                   // [N, 2, 1024]

    const int N = in_sizes[0] / (512 * 9);

    constexpr int SMEM0 = 2 * 512  * 9 * 4;   // 36 KB
    constexpr int SMEM1 = 2 * 1024 * 9 * 4;   // 72 KB

    cudaFuncSetAttribute(gram_kernel<512>,
                         cudaFuncAttributeMaxDynamicSharedMemorySize, SMEM0);
    cudaFuncSetAttribute(gram_kernel<1024>,
                         cudaFuncAttributeMaxDynamicSharedMemorySize, SMEM1);

    const int grid = 296;   // 2 persistent CTAs per SM
    gram_kernel<512> <<<grid, 256, SMEM0>>>(feat0, out, 0, N);
    gram_kernel<1024><<<grid, 256, SMEM1>>>(feat1, out, 1, N);
}